// round 14
// baseline (speedup 1.0000x reference)
#include <cuda_runtime.h>
#include <cuda_bf16.h>
#include <cstdint>
#include <math.h>

#define EPSR 1e-6f
#define NSAMP 256
#define PITCH 204

// ---------------- global scratch (static; no allocation) ----------
__device__ float g_S[NSAMP * 196 * PITCH];   // per-sample Gram, row-major pitch 204
__device__ float g_P[NSAMP * 196 * 4];       // final projection (A = T0 @ P)

__device__ __forceinline__ uint32_t smem_u32(const void* p) {
    uint32_t a;
    asm("{ .reg .u64 t; cvta.to.shared.u64 t, %1; cvt.u32.u64 %0, t; }" : "=r"(a) : "l"(p));
    return a;
}

// Warp-parallel 4x4 SPD inverse via adjugate (lanes 0..15)
__device__ __forceinline__ void inv4_warp16(const float* __restrict__ ga,
                                            const float* __restrict__ gb,
                                            float* __restrict__ gi, int t)
{
    float G[16];
#pragma unroll
    for (int e = 0; e < 16; e++)
        G[e] = ga[e] * gb[e] + ((e % 5 == 0) ? EPSR : 0.f);
    int i = t >> 2, j = t & 3;
    int r0 = (i == 0) ? 1 : 0, r1 = (i < 2) ? 2 : 1, r2 = (i < 3) ? 3 : 2;
    int c0 = (j == 0) ? 1 : 0, c1 = (j < 2) ? 2 : 1, c2 = (j < 3) ? 3 : 2;
    float a = G[r0 * 4 + c0], bb = G[r0 * 4 + c1], c = G[r0 * 4 + c2];
    float d = G[r1 * 4 + c0], e  = G[r1 * 4 + c1], f = G[r1 * 4 + c2];
    float g = G[r2 * 4 + c0], h  = G[r2 * 4 + c1], i2 = G[r2 * 4 + c2];
    float det3 = a * (e * i2 - f * h) - bb * (d * i2 - f * g) + c * (d * h - e * g);
    float cof = ((i + j) & 1) ? -det3 : det3;
    const unsigned m16 = 0x0000ffffu;
    float c0v = __shfl_sync(m16, cof, 0);
    float c1v = __shfl_sync(m16, cof, 1);
    float c2v = __shfl_sync(m16, cof, 2);
    float c3v = __shfl_sync(m16, cof, 3);
    float det = G[0] * c0v + G[1] * c1v + G[2] * c2v + G[3] * c3v;
    float cji = __shfl_sync(m16, cof, j * 4 + i);
    gi[t] = cji / det;
}

#define MMA_BF16(D, A, B)                                                         \
    asm volatile("mma.sync.aligned.m16n8k16.row.col.f32.bf16.bf16.f32 "           \
        "{%0,%1,%2,%3}, {%4,%5,%6,%7}, {%8,%9}, {%0,%1,%2,%3};"                   \
        : "+f"((D)[0]), "+f"((D)[1]), "+f"((D)[2]), "+f"((D)[3])                  \
        : "r"((A)[0]), "r"((A)[1]), "r"((A)[2]), "r"((A)[3]),                     \
          "r"((B)[0]), "r"((B)[1]))

#define LDM_X4(R, ADDR)                                                           \
    asm volatile("ldmatrix.sync.aligned.m8n8.x4.shared.b16 {%0,%1,%2,%3}, [%4];"  \
        : "=r"((R)[0]), "=r"((R)[1]), "=r"((R)[2]), "=r"((R)[3]) : "r"(ADDR))

#define LDM_X2(R, ADDR)                                                           \
    asm volatile("ldmatrix.sync.aligned.m8n8.x2.shared.b16 {%0,%1}, [%2];"        \
        : "=r"((R)[0]), "=r"((R)[1]) : "r"(ADDR))

// =====================================================================
// K1: S = T0^T T0 via mma.sync (bf16 two-term split).
// Grid 2*NSAMP: CTA (b, half) computes n-tiles [0,13) or [13,25).
// 2 CTAs/SM.  Tiles written from accumulators to g_S (pitch 204).
// =====================================================================
#define K1_STG  0
#define K1_AHI  6472
#define K1_ALO  12296
#define K1_FLOATS 18120       // 72480 B

extern __shared__ float sm[];

template<int NI0, int NT>
__device__ __forceinline__ void gram_pass(const float* __restrict__ xs,
                                          float* __restrict__ gS,
                                          int t, int wid, int lane,
                                          uint32_t ahi_u32, uint32_t alo_u32)
{
    float acc[NT][4];
#pragma unroll
    for (int i = 0; i < NT; i++) {
        acc[i][0] = 0.f; acc[i][1] = 0.f; acc[i][2] = 0.f; acc[i][3] = 0.f;
    }
    float* stgT = sm + K1_STG;
    __nv_bfloat16* AH = (__nv_bfloat16*)(sm + K1_AHI);
    __nv_bfloat16* AL = (__nv_bfloat16*)(sm + K1_ALO);
    const int mi = wid;

    for (int ch = 0; ch < 16; ++ch) {
        // stage 32 channels x 196 floats TRANSPOSED: stg_T[i][c], pitch 33
        {
            const float4* src = (const float4*)(xs + ch * 32 * 196);
            for (int v = t; v < 1568; v += 512) {
                int c = v / 49, i4 = v - 49 * c;
                float4 xv = src[v];
                float* d = stgT + (i4 * 4) * 33 + c;
                d[0]  = xv.x;
                d[33] = xv.y;
                d[66] = xv.z;
                d[99] = xv.w;
            }
        }
        __syncthreads();
        // convert to bf16 hi/lo: conflict-free row reads, contiguous stores
        for (int r = wid; r < 196; r += 16) {
            float v0 = stgT[r * 33 + lane];
            __nv_bfloat16 h = __float2bfloat16(v0);
            float hf = __bfloat162float(h);
            __nv_bfloat16 l = __float2bfloat16(v0 - hf);
            AH[r * 56 + lane] = h;
            AL[r * 56 + lane] = l;
        }
        __syncthreads();
        if (wid < 13) {
#pragma unroll
            for (int k16 = 0; k16 < 2; ++k16) {
                const int kof = k16 * 16;
                uint32_t aoff = (uint32_t)((mi * 16 + (lane & 15)) * 112 +
                                           (kof + ((lane >> 4) << 3)) * 2);
                uint32_t ah[4], al[4];
                LDM_X4(ah, ahi_u32 + aoff);
                LDM_X4(al, alo_u32 + aoff);
                uint32_t boff = (uint32_t)((lane & 7) * 112 + (kof + (lane & 8)) * 2);
#pragma unroll
                for (int nt = 0; nt < NT; ++nt) {
                    uint32_t bo = boff + (uint32_t)((NI0 + nt) * 8 * 112);
                    uint32_t bh[2], bl[2];
                    LDM_X2(bh, ahi_u32 + bo);
                    LDM_X2(bl, alo_u32 + bo);
                    MMA_BF16(acc[nt], ah, bh);
                    MMA_BF16(acc[nt], ah, bl);
                    MMA_BF16(acc[nt], al, bh);
                }
            }
        }
        __syncthreads();
    }
    // epilogue: registers -> g_S (row-major pitch 204, float2 stores)
    if (wid < 13) {
        int r0 = mi * 16 + (lane >> 2);
        int r1 = r0 + 8;
#pragma unroll
        for (int nt = 0; nt < NT; ++nt) {
            int cn = (NI0 + nt) * 8 + (lane & 3) * 2;
            if (cn < 196) {
                if (r0 < 196) *(float2*)(gS + r0 * PITCH + cn) = make_float2(acc[nt][0], acc[nt][1]);
                if (r1 < 196) *(float2*)(gS + r1 * PITCH + cn) = make_float2(acc[nt][2], acc[nt][3]);
            }
        }
    }
}

__global__ void __launch_bounds__(512, 2)
k1_gram(const float* __restrict__ x)
{
    const int b = blockIdx.x >> 1;
    const int half = blockIdx.x & 1;
    const int t = threadIdx.x;
    const int wid = t >> 5, lane = t & 31;
    const float* xs = x + (size_t)b * 100352;
    float* gS = g_S + (size_t)b * 196 * PITCH;

    const uint32_t ahi_u32 = smem_u32(sm + K1_AHI);
    const uint32_t alo_u32 = smem_u32(sm + K1_ALO);

    // zero pad rows 196..207 (cols 0..31) of AHI/ALO
    {
        __nv_bfloat16* AH = (__nv_bfloat16*)(sm + K1_AHI);
        __nv_bfloat16* AL = (__nv_bfloat16*)(sm + K1_ALO);
        __nv_bfloat16 z = __float2bfloat16(0.f);
        if (t < 384) {
            int r = 196 + (t >> 5), c = t & 31;
            AH[r * 56 + c] = z;
            AL[r * 56 + c] = z;
        }
    }
    if (half == 0) gram_pass<0, 13>(xs, gS, t, wid, lane, ahi_u32, alo_u32);
    else           gram_pass<13, 12>(xs, gS, t, wid, lane, ahi_u32, alo_u32);
}

// =====================================================================
// K2: 20 ALS iterations on smem-resident S; 1024 threads (32 warps/SM),
// Q-loop 4-way q-split (784 active threads).  Writes final P to g_P.
// =====================================================================
#define K2_S    0             // 39984
#define K2_QP   39984         // 4 planes x 788 = 3152 -> 43136
#define K2_Q    43136         // 784
#define K2_P    43920         // 784
#define K2_B    44704
#define K2_C    44760
#define K2_BTB  44816
#define K2_CTC  44832
#define K2_ATA  44848
#define K2_GI   44864
#define K2_M    44880         // 56 -> 44936
#define K2_REDA 44936         // 224 -> 45160
#define K2_FLOATS 45160       // 180640 B

__global__ void __launch_bounds__(1024, 1)
k2_als(const float* __restrict__ B0, const float* __restrict__ C0)
{
    const int b = blockIdx.x;
    const int t = threadIdx.x;

    float* S = sm + K2_S;
    float* Qpart = sm + K2_QP;
    float* Q = sm + K2_Q;
    float* sP = sm + K2_P;
    float* sB = sm + K2_B;
    float* sC = sm + K2_C;
    float* sBtB = sm + K2_BTB;
    float* sCtC = sm + K2_CTC;
    float* sAtA = sm + K2_ATA;
    float* sGi = sm + K2_GI;
    float* sM = sm + K2_M;
    float* redA = sm + K2_REDA;

    // load S (coalesced f4) and init factors
    {
        const float4* gS4 = (const float4*)(g_S + (size_t)b * 196 * PITCH);
        float4* Ss4 = (float4*)S;
        for (int v = t; v < 9996; v += 1024) Ss4[v] = gS4[v];
    }
    if (t >= 800 && t < 856) sB[t - 800] = B0[b * 56 + (t - 800)];
    else if (t >= 856 && t < 912) sC[t - 856] = C0[b * 56 + (t - 856)];
    __syncthreads();

    for (int it = 0; it < 20; it++) {
        if (t < 32) {
            int which = t >> 4, e = t & 15, a = e >> 2, c2 = e & 3;
            const float* F = which ? sC : sB;
            float s = 0.f;
#pragma unroll
            for (int j = 0; j < 14; j++) s += F[j * 4 + a] * F[j * 4 + c2];
            (which ? sCtC : sBtB)[e] = s;
            __syncwarp();
            if (t < 16) inv4_warp16(sBtB, sCtC, sGi, t);
        }
        __syncthreads();
        if (t < 196) {
            int j = t / 14, k = t - (t / 14) * 14;
            float kr0 = sB[j * 4 + 0] * sC[k * 4 + 0];
            float kr1 = sB[j * 4 + 1] * sC[k * 4 + 1];
            float kr2 = sB[j * 4 + 2] * sC[k * 4 + 2];
            float kr3 = sB[j * 4 + 3] * sC[k * 4 + 3];
#pragma unroll
            for (int r = 0; r < 4; r++)
                sP[t * 4 + r] = kr0 * sGi[0 * 4 + r] + kr1 * sGi[1 * 4 + r] +
                                kr2 * sGi[2 * 4 + r] + kr3 * sGi[3 * 4 + r];
        }
        __syncthreads();
        if (it == 19) break;                // final A needs only P

        // Q = S @ P: 784 threads, row p, quarter qu of the 49 f4-groups
        if (t < 784) {
            int qu = t / 196;
            int p = t - qu * 196;
            const float* srow = S + p * PITCH;
            const float4* Pv = (const float4*)sP;
            float a0 = 0, a1 = 0, a2 = 0, a3 = 0;
            int f0 = (qu == 0) ? 0 : (qu * 12 + 1);   // 0,13,25,37
            int f1 = qu * 12 + 13;                    // 13,25,37,49
#pragma unroll 4
            for (int f = f0; f < f1; ++f) {
                float4 sv = *(const float4*)(srow + f * 4);
                float4 p0 = Pv[f * 4 + 0];
                float4 p1 = Pv[f * 4 + 1];
                float4 p2 = Pv[f * 4 + 2];
                float4 p3 = Pv[f * 4 + 3];
                a0 += sv.x * p0.x + sv.y * p1.x + sv.z * p2.x + sv.w * p3.x;
                a1 += sv.x * p0.y + sv.y * p1.y + sv.z * p2.y + sv.w * p3.y;
                a2 += sv.x * p0.z + sv.y * p1.z + sv.z * p2.z + sv.w * p3.z;
                a3 += sv.x * p0.w + sv.y * p1.w + sv.z * p2.w + sv.w * p3.w;
            }
            *(float4*)(Qpart + qu * 788 + p * 4) = make_float4(a0, a1, a2, a3);
        }
        __syncthreads();
        if (t < 196) {
            float4 q0 = *(const float4*)(Qpart + 0 * 788 + t * 4);
            float4 q1 = *(const float4*)(Qpart + 1 * 788 + t * 4);
            float4 q2 = *(const float4*)(Qpart + 2 * 788 + t * 4);
            float4 q3 = *(const float4*)(Qpart + 3 * 788 + t * 4);
            *(float4*)(Q + t * 4) = make_float4(q0.x + q1.x + q2.x + q3.x,
                                                q0.y + q1.y + q2.y + q3.y,
                                                q0.z + q1.z + q2.z + q3.z,
                                                q0.w + q1.w + q2.w + q3.w);
        }
        __syncthreads();
        if (t < 224) {
            int e = t / 14, c = t - (t / 14) * 14;
            int s_ = e >> 2, r = e & 3;
            float v = 0.f;
            int pb = c * 14;
#pragma unroll
            for (int p = 0; p < 14; p++) v += sP[(pb + p) * 4 + s_] * Q[(pb + p) * 4 + r];
            redA[e * 14 + c] = v;
        } else if (t >= 256 && t < 312) {
            int e = t - 256; int j = e >> 2, r = e & 3;
            float v = 0.f;
#pragma unroll
            for (int k = 0; k < 14; k++) v += sC[k * 4 + r] * Q[(j * 14 + k) * 4 + r];
            sM[e] = v;
        }
        __syncthreads();
        if (t < 32) {
            if (t < 16) {
                float v = 0.f;
#pragma unroll
                for (int c = 0; c < 14; c++) v += redA[t * 14 + c];
                sAtA[t] = v;
            }
            __syncwarp();
            if (t < 16) inv4_warp16(sAtA, sCtC, sGi, t);
        }
        __syncthreads();
        if (t < 56) {
            int j = t >> 2, r = t & 3;
            sB[t] = sM[j * 4 + 0] * sGi[0 * 4 + r] + sM[j * 4 + 1] * sGi[1 * 4 + r] +
                    sM[j * 4 + 2] * sGi[2 * 4 + r] + sM[j * 4 + 3] * sGi[3 * 4 + r];
        }
        __syncthreads();
        if (t < 32) {
            if (t < 16) {
                int a = t >> 2, c2 = t & 3;
                float s = 0.f;
#pragma unroll
                for (int j = 0; j < 14; j++) s += sB[j * 4 + a] * sB[j * 4 + c2];
                sBtB[t] = s;
            }
            __syncwarp();
            if (t < 16) inv4_warp16(sAtA, sBtB, sGi, t);
        } else if (t >= 64 && t < 120) {
            int e = t - 64; int k = e >> 2, r = e & 3;
            float v = 0.f;
#pragma unroll
            for (int j = 0; j < 14; j++) v += sB[j * 4 + r] * Q[(j * 14 + k) * 4 + r];
            sM[e] = v;
        }
        __syncthreads();
        if (t < 56) {
            int k = t >> 2, r = t & 3;
            sC[t] = sM[k * 4 + 0] * sGi[0 * 4 + r] + sM[k * 4 + 1] * sGi[1 * 4 + r] +
                    sM[k * 4 + 2] * sGi[2 * 4 + r] + sM[k * 4 + 3] * sGi[3 * 4 + r];
        }
        __syncthreads();
    }

    if (t < 196)
        ((float4*)(g_P + (size_t)b * 784))[t] = *(const float4*)(sP + t * 4);
}

// =====================================================================
// K3: A = T0@Pt (smem-staged x), rank_fc, SE gate, APPLY. 2 CTAs/SM.
// (unchanged from round 13)
// =====================================================================
#define A_TC   0              // staging [64][50] f4 = 12800 floats
#define A_PT   12800          // Pt [4][196] = 784
#define A_Y2   13584
#define A_RED  14096
#define A_Z    14608
#define A_W1   14640
#define A_W2   14656
#define A_G    14660          // gate [512]
#define A_FLOATS 15172        // 60688 B

__global__ void __launch_bounds__(512, 2)
k3_gate_apply(const float* __restrict__ x, const float* __restrict__ w1,
              const float* __restrict__ w2, const float* __restrict__ fw1,
              const float* __restrict__ fw2, float* __restrict__ out)
{
    const int b = blockIdx.x;
    const int t = threadIdx.x;
    const int wid = t >> 5, lane = t & 31;
    const float* xs = x + (size_t)b * 100352;

    float4* Tc4 = (float4*)(sm + A_TC);
    float* Pt = sm + A_PT;
    float* sy2 = sm + A_Y2;
    float* red = sm + A_RED;
    float* sz = sm + A_Z;
    float* sw1 = sm + A_W1;
    float* sw2 = sm + A_W2;
    float* sg = sm + A_G;

    if (t < 196) {
        float4 p = ((const float4*)(g_P + (size_t)b * 784))[t];
        Pt[t] = p.x; Pt[196 + t] = p.y; Pt[392 + t] = p.z; Pt[588 + t] = p.w;
    } else if (t >= 448 && t < 464) sw1[t - 448] = w1[t - 448];
    else if (t >= 464 && t < 468) sw2[t - 464] = w2[t - 464];

    const int cl = t >> 3;                  // channel-within-chunk 0..63
    const int s = t & 7;                    // col-slice (7 active)
    __syncthreads();

    for (int ch = 0; ch < 8; ch++) {
        for (int v = t; v < 3200; v += 512) {
            int i = v / 50, c4 = v - 50 * (v / 50);
            if (c4 < 49)
                Tc4[i * 50 + c4] = *(const float4*)(xs + ch * 12544 + i * 196 + c4 * 4);
        }
        __syncthreads();
        float a0 = 0, a1 = 0, a2 = 0, a3 = 0;
        if (s < 7) {
            const float* row = sm + A_TC + cl * 200;
#pragma unroll
            for (int j = 0; j < 7; j++) {
                int q = s * 28 + j * 4;
                float4 xv = *(const float4*)(row + q);
                float4 p0 = *(const float4*)(Pt + q);
                float4 p1 = *(const float4*)(Pt + 196 + q);
                float4 p2 = *(const float4*)(Pt + 392 + q);
                float4 p3 = *(const float4*)(Pt + 588 + q);
                a0 += xv.x * p0.x + xv.y * p0.y + xv.z * p0.z + xv.w * p0.w;
                a1 += xv.x * p1.x + xv.y * p1.y + xv.z * p1.z + xv.w * p1.w;
                a2 += xv.x * p2.x + xv.y * p2.y + xv.z * p2.z + xv.w * p2.w;
                a3 += xv.x * p3.x + xv.y * p3.y + xv.z * p3.z + xv.w * p3.w;
            }
        }
#pragma unroll
        for (int m = 4; m; m >>= 1) {
            a0 += __shfl_xor_sync(0xffffffffu, a0, m);
            a1 += __shfl_xor_sync(0xffffffffu, a1, m);
            a2 += __shfl_xor_sync(0xffffffffu, a2, m);
            a3 += __shfl_xor_sync(0xffffffffu, a3, m);
        }
        if (s == 0) {
            float y2 = 0.f;
#pragma unroll
            for (int s_ = 0; s_ < 4; s_++) {
                float u = a0 * sw1[s_ * 4 + 0] + a1 * sw1[s_ * 4 + 1] +
                          a2 * sw1[s_ * 4 + 2] + a3 * sw1[s_ * 4 + 3];
                u = fmaxf(u, 0.f);
                y2 += u * sw2[s_];
            }
            sy2[ch * 64 + cl] = y2;
        }
        __syncthreads();
    }
    // z = relu(fw1 @ y2)
    {
        int m = t >> 4, c = t & 15;
        const float* fr = fw1 + m * 512 + c * 32;
        const float* yy = sy2 + c * 32;
        float v = 0.f;
#pragma unroll
        for (int i2 = 0; i2 < 32; i2++) v += fr[i2] * yy[i2];
        red[m * 16 + c] = v;
    }
    __syncthreads();
    if (t < 32) {
        float v = 0.f;
#pragma unroll
        for (int c = 0; c < 16; c++) v += red[t * 16 + c];
        sz[t] = fmaxf(v, 0.f);
    }
    __syncthreads();
    {
        const float* fr = fw2 + t * 32;
        float v = 0.f;
#pragma unroll
        for (int m = 0; m < 32; m++) v += fr[m] * sz[m];
        sg[t] = 1.f / (1.f + expf(-v));
    }
    __syncthreads();
    // apply gate: out = x * g[channel]; x re-read from L2 (just staged)
    {
        const float4* xin4 = (const float4*)xs;
        float4* out4 = (float4*)(out + (size_t)b * 100352);
        for (int c = wid; c < 512; c += 16) {
            float g = sg[c];
            const float4* xr = xin4 + c * 49;
            float4* orow = out4 + c * 49;
            float4 xv = xr[lane];
            if (lane < 17) {
                float4 xv2 = xr[lane + 32];
                orow[lane + 32] = make_float4(xv2.x * g, xv2.y * g, xv2.z * g, xv2.w * g);
            }
            orow[lane] = make_float4(xv.x * g, xv.y * g, xv.z * g, xv.w * g);
        }
    }
}

extern "C" void kernel_launch(void* const* d_in, const int* in_sizes, int n_in,
                              void* d_out, int out_size) {
    const float* x   = (const float*)d_in[0];
    // d_in[1] = A0: unused (A is overwritten before first use in the reference)
    const float* B0  = (const float*)d_in[2];
    const float* C0  = (const float*)d_in[3];
    const float* w1  = (const float*)d_in[4];
    const float* w2  = (const float*)d_in[5];
    const float* fw1 = (const float*)d_in[6];
    const float* fw2 = (const float*)d_in[7];
    float* out = (float*)d_out;

    int b = in_sizes[0] / 100352;                        // 256
    size_t sm1 = (size_t)K1_FLOATS * sizeof(float);      // 72480
    size_t sm2 = (size_t)K2_FLOATS * sizeof(float);      // 180640
    size_t sm3 = (size_t)A_FLOATS * sizeof(float);       // 60688
    static int configured = 0;
    if (!configured) {
        cudaFuncSetAttribute(k1_gram,       cudaFuncAttributeMaxDynamicSharedMemorySize, (int)sm1);
        cudaFuncSetAttribute(k2_als,        cudaFuncAttributeMaxDynamicSharedMemorySize, (int)sm2);
        cudaFuncSetAttribute(k3_gate_apply, cudaFuncAttributeMaxDynamicSharedMemorySize, (int)sm3);
        configured = 1;
    }
    k1_gram<<<2 * b, 512, sm1>>>(x);
    k2_als<<<b, 1024, sm2>>>(B0, C0);
    k3_gate_apply<<<b, 512, sm3>>>(x, w1, w2, fw1, fw2, out);
}

// round 15
// speedup vs baseline: 1.0285x; 1.0285x over previous
#include <cuda_runtime.h>
#include <cuda_bf16.h>
#include <cstdint>
#include <math.h>

#define EPSR 1e-6f
#define NSAMP 256

// ---------------- global scratch (static; no allocation) ----------
// S in float4-panel layout: panel g (g<49) holds cols 4g..4g+3 for all 196 rows:
//   addr(p, 4g+j) = g*784 + p*4 + j   (lane-consecutive p -> coalesced f4 reads)
__device__ float g_Sc[NSAMP * 49 * 784];     // 38416 f/sample (L2-resident)
__device__ float g_P[NSAMP * 196 * 4];       // final projection (A = T0 @ P)

__device__ __forceinline__ uint32_t smem_u32(const void* p) {
    uint32_t a;
    asm("{ .reg .u64 t; cvta.to.shared.u64 t, %1; cvt.u32.u64 %0, t; }" : "=r"(a) : "l"(p));
    return a;
}

// Warp-parallel 4x4 SPD inverse via adjugate (lanes 0..15)
__device__ __forceinline__ void inv4_warp16(const float* __restrict__ ga,
                                            const float* __restrict__ gb,
                                            float* __restrict__ gi, int t)
{
    float G[16];
#pragma unroll
    for (int e = 0; e < 16; e++)
        G[e] = ga[e] * gb[e] + ((e % 5 == 0) ? EPSR : 0.f);
    int i = t >> 2, j = t & 3;
    int r0 = (i == 0) ? 1 : 0, r1 = (i < 2) ? 2 : 1, r2 = (i < 3) ? 3 : 2;
    int c0 = (j == 0) ? 1 : 0, c1 = (j < 2) ? 2 : 1, c2 = (j < 3) ? 3 : 2;
    float a = G[r0 * 4 + c0], bb = G[r0 * 4 + c1], c = G[r0 * 4 + c2];
    float d = G[r1 * 4 + c0], e  = G[r1 * 4 + c1], f = G[r1 * 4 + c2];
    float g = G[r2 * 4 + c0], h  = G[r2 * 4 + c1], i2 = G[r2 * 4 + c2];
    float det3 = a * (e * i2 - f * h) - bb * (d * i2 - f * g) + c * (d * h - e * g);
    float cof = ((i + j) & 1) ? -det3 : det3;
    const unsigned m16 = 0x0000ffffu;
    float c0v = __shfl_sync(m16, cof, 0);
    float c1v = __shfl_sync(m16, cof, 1);
    float c2v = __shfl_sync(m16, cof, 2);
    float c3v = __shfl_sync(m16, cof, 3);
    float det = G[0] * c0v + G[1] * c1v + G[2] * c2v + G[3] * c3v;
    float cji = __shfl_sync(m16, cof, j * 4 + i);
    gi[t] = cji / det;
}

#define MMA_BF16(D, A, B)                                                         \
    asm volatile("mma.sync.aligned.m16n8k16.row.col.f32.bf16.bf16.f32 "           \
        "{%0,%1,%2,%3}, {%4,%5,%6,%7}, {%8,%9}, {%0,%1,%2,%3};"                   \
        : "+f"((D)[0]), "+f"((D)[1]), "+f"((D)[2]), "+f"((D)[3])                  \
        : "r"((A)[0]), "r"((A)[1]), "r"((A)[2]), "r"((A)[3]),                     \
          "r"((B)[0]), "r"((B)[1]))

#define LDM_X4(R, ADDR)                                                           \
    asm volatile("ldmatrix.sync.aligned.m8n8.x4.shared.b16 {%0,%1,%2,%3}, [%4];"  \
        : "=r"((R)[0]), "=r"((R)[1]), "=r"((R)[2]), "=r"((R)[3]) : "r"(ADDR))

#define LDM_X2(R, ADDR)                                                           \
    asm volatile("ldmatrix.sync.aligned.m8n8.x2.shared.b16 {%0,%1}, [%2];"        \
        : "=r"((R)[0]), "=r"((R)[1]) : "r"(ADDR))

// =====================================================================
// K1: S = T0^T T0 via mma.sync (bf16 two-term split).  (round-13 exact)
// Grid 2*NSAMP: CTA (b, half) computes n-tiles [0,13) or [13,25).
// =====================================================================
#define K1_STG  0
#define K1_AHI  6472
#define K1_ALO  12296
#define K1_FLOATS 18120       // 72480 B

extern __shared__ float sm[];

template<int NI0, int NT>
__device__ __forceinline__ void gram_pass(const float* __restrict__ xs,
                                          float* __restrict__ gS,
                                          int t, int wid, int lane,
                                          uint32_t ahi_u32, uint32_t alo_u32)
{
    float acc[NT][4];
#pragma unroll
    for (int i = 0; i < NT; i++) {
        acc[i][0] = 0.f; acc[i][1] = 0.f; acc[i][2] = 0.f; acc[i][3] = 0.f;
    }
    float* stgT = sm + K1_STG;
    __nv_bfloat16* AH = (__nv_bfloat16*)(sm + K1_AHI);
    __nv_bfloat16* AL = (__nv_bfloat16*)(sm + K1_ALO);
    const int mi = wid;

    for (int ch = 0; ch < 16; ++ch) {
        {
            const float4* src = (const float4*)(xs + ch * 32 * 196);
            for (int v = t; v < 1568; v += 512) {
                int c = v / 49, i4 = v - 49 * c;
                float4 xv = src[v];
                float* d = stgT + (i4 * 4) * 33 + c;
                d[0]  = xv.x;
                d[33] = xv.y;
                d[66] = xv.z;
                d[99] = xv.w;
            }
        }
        __syncthreads();
        for (int r = wid; r < 196; r += 16) {
            float v0 = stgT[r * 33 + lane];
            __nv_bfloat16 h = __float2bfloat16(v0);
            float hf = __bfloat162float(h);
            __nv_bfloat16 l = __float2bfloat16(v0 - hf);
            AH[r * 56 + lane] = h;
            AL[r * 56 + lane] = l;
        }
        __syncthreads();
        if (wid < 13) {
#pragma unroll
            for (int k16 = 0; k16 < 2; ++k16) {
                const int kof = k16 * 16;
                uint32_t aoff = (uint32_t)((mi * 16 + (lane & 15)) * 112 +
                                           (kof + ((lane >> 4) << 3)) * 2);
                uint32_t ah[4], al[4];
                LDM_X4(ah, ahi_u32 + aoff);
                LDM_X4(al, alo_u32 + aoff);
                uint32_t boff = (uint32_t)((lane & 7) * 112 + (kof + (lane & 8)) * 2);
#pragma unroll
                for (int nt = 0; nt < NT; ++nt) {
                    uint32_t bo = boff + (uint32_t)((NI0 + nt) * 8 * 112);
                    uint32_t bh[2], bl[2];
                    LDM_X2(bh, ahi_u32 + bo);
                    LDM_X2(bl, alo_u32 + bo);
                    MMA_BF16(acc[nt], ah, bh);
                    MMA_BF16(acc[nt], ah, bl);
                    MMA_BF16(acc[nt], al, bh);
                }
            }
        }
        __syncthreads();
    }
    // epilogue: registers -> g_Sc panels (float2 stores, 8B aligned)
    if (wid < 13) {
        int r0 = mi * 16 + (lane >> 2);
        int r1 = r0 + 8;
#pragma unroll
        for (int nt = 0; nt < NT; ++nt) {
            int cn = (NI0 + nt) * 8 + (lane & 3) * 2;   // even, < 200
            if (cn < 196) {
                int base = (cn >> 2) * 784 + (cn & 3);
                if (r0 < 196) *(float2*)(gS + base + r0 * 4) = make_float2(acc[nt][0], acc[nt][1]);
                if (r1 < 196) *(float2*)(gS + base + r1 * 4) = make_float2(acc[nt][2], acc[nt][3]);
            }
        }
    }
}

__global__ void __launch_bounds__(512, 2)
k1_gram(const float* __restrict__ x)
{
    const int b = blockIdx.x >> 1;
    const int half = blockIdx.x & 1;
    const int t = threadIdx.x;
    const int wid = t >> 5, lane = t & 31;
    const float* xs = x + (size_t)b * 100352;
    float* gS = g_Sc + (size_t)b * 38416;

    const uint32_t ahi_u32 = smem_u32(sm + K1_AHI);
    const uint32_t alo_u32 = smem_u32(sm + K1_ALO);

    {
        __nv_bfloat16* AH = (__nv_bfloat16*)(sm + K1_AHI);
        __nv_bfloat16* AL = (__nv_bfloat16*)(sm + K1_ALO);
        __nv_bfloat16 z = __float2bfloat16(0.f);
        if (t < 384) {
            int r = 196 + (t >> 5), c = t & 31;
            AH[r * 56 + c] = z;
            AL[r * 56 + c] = z;
        }
    }
    if (half == 0) gram_pass<0, 13>(xs, gS, t, wid, lane, ahi_u32, alo_u32);
    else           gram_pass<13, 12>(xs, gS, t, wid, lane, ahi_u32, alo_u32);
}

// =====================================================================
// K2: 20 ALS iterations.  HYBRID S: panels 0-14 & 24-38 cached in smem
// (30 panels, 94 KB), panels 15-23 & 39-48 streamed from L2.
// Shape unchanged from round 13: 512 thr, 2 CTAs/SM, single wave.
// =====================================================================
#define K2_SP   0             // smem panels [30][196] f4 = 23520 floats
#define K2_Q    23520
#define K2_QP   24304         // 1568 -> 25872
#define K2_P    25872
#define K2_B    26656
#define K2_C    26712
#define K2_BTB  26768
#define K2_CTC  26784
#define K2_ATA  26800
#define K2_GI   26816
#define K2_M    26832
#define K2_REDA 26888         // 224 -> 27112
#define K2_FLOATS 27112       // 108448 B; x2 CTAs = 216896 <= 232448

__global__ void __launch_bounds__(512, 2)
k2_als(const float* __restrict__ B0, const float* __restrict__ C0)
{
    const int b = blockIdx.x;
    const int t = threadIdx.x;

    float4* sp4 = (float4*)(sm + K2_SP);     // [30][196]
    float* Q = sm + K2_Q;
    float* Qpart = sm + K2_QP;
    float* sP = sm + K2_P;
    float* sB = sm + K2_B;
    float* sC = sm + K2_C;
    float* sBtB = sm + K2_BTB;
    float* sCtC = sm + K2_CTC;
    float* sAtA = sm + K2_ATA;
    float* sGi = sm + K2_GI;
    float* sM = sm + K2_M;
    float* redA = sm + K2_REDA;

    const float4* Sp = (const float4*)(g_Sc + (size_t)b * 38416);  // [49][196] f4

    // load 30 cached panels: slots 0..14 = g 0..14 ; slots 15..29 = g 24..38
    for (int v = t; v < 5880; v += 512) {
        int s = v / 196, p = v - s * 196;
        int g = (s < 15) ? s : (s + 9);
        sp4[v] = Sp[g * 196 + p];
    }
    if (t >= 400 && t < 456) sB[t - 400] = B0[b * 56 + (t - 400)];
    else if (t >= 456 && t < 512) sC[t - 456] = C0[b * 56 + (t - 456)];
    __syncthreads();

    for (int it = 0; it < 20; it++) {
        if (t < 32) {
            int which = t >> 4, e = t & 15, a = e >> 2, c2 = e & 3;
            const float* F = which ? sC : sB;
            float s = 0.f;
#pragma unroll
            for (int j = 0; j < 14; j++) s += F[j * 4 + a] * F[j * 4 + c2];
            (which ? sCtC : sBtB)[e] = s;
            __syncwarp();
            if (t < 16) inv4_warp16(sBtB, sCtC, sGi, t);
        }
        __syncthreads();
        if (t < 196) {
            int j = t / 14, k = t - (t / 14) * 14;
            float kr0 = sB[j * 4 + 0] * sC[k * 4 + 0];
            float kr1 = sB[j * 4 + 1] * sC[k * 4 + 1];
            float kr2 = sB[j * 4 + 2] * sC[k * 4 + 2];
            float kr3 = sB[j * 4 + 3] * sC[k * 4 + 3];
#pragma unroll
            for (int r = 0; r < 4; r++)
                sP[t * 4 + r] = kr0 * sGi[0 * 4 + r] + kr1 * sGi[1 * 4 + r] +
                                kr2 * sGi[2 * 4 + r] + kr3 * sGi[3 * 4 + r];
        }
        __syncthreads();
        if (it == 19) break;                // final A needs only P

        // Q = S @ P; half A: g 0..23 (15 smem + 9 L2), half B: g 24..48 (15 smem + 10 L2)
        if (t < 392) {
            int p = (t < 196) ? t : (t - 196);
            const float4* Pv = (const float4*)sP;
            float a0 = 0, a1 = 0, a2 = 0, a3 = 0;
#define QSTEP_SV(sv, g)                                                        \
            {                                                                  \
                float4 p0 = Pv[(g) * 4 + 0];                                   \
                float4 p1 = Pv[(g) * 4 + 1];                                   \
                float4 p2 = Pv[(g) * 4 + 2];                                   \
                float4 p3 = Pv[(g) * 4 + 3];                                   \
                a0 += sv.x * p0.x + sv.y * p1.x + sv.z * p2.x + sv.w * p3.x;   \
                a1 += sv.x * p0.y + sv.y * p1.y + sv.z * p2.y + sv.w * p3.y;   \
                a2 += sv.x * p0.z + sv.y * p1.z + sv.z * p2.z + sv.w * p3.z;   \
                a3 += sv.x * p0.w + sv.y * p1.w + sv.z * p2.w + sv.w * p3.w;   \
            }
            if (t < 196) {
#pragma unroll
                for (int g = 0; g < 15; ++g) {           // smem slots 0..14
                    float4 sv = sp4[g * 196 + p];
                    QSTEP_SV(sv, g);
                }
#pragma unroll
                for (int g = 15; g < 24; ++g) {          // L2
                    float4 sv = __ldg(Sp + g * 196 + p);
                    QSTEP_SV(sv, g);
                }
                Qpart[p * 8 + 0] = a0; Qpart[p * 8 + 1] = a1;
                Qpart[p * 8 + 2] = a2; Qpart[p * 8 + 3] = a3;
            } else {
#pragma unroll
                for (int g = 24; g < 39; ++g) {          // smem slots 15..29
                    float4 sv = sp4[(g - 9) * 196 + p];
                    QSTEP_SV(sv, g);
                }
#pragma unroll
                for (int g = 39; g < 49; ++g) {          // L2
                    float4 sv = __ldg(Sp + g * 196 + p);
                    QSTEP_SV(sv, g);
                }
                Qpart[p * 8 + 4] = a0; Qpart[p * 8 + 5] = a1;
                Qpart[p * 8 + 6] = a2; Qpart[p * 8 + 7] = a3;
            }
#undef QSTEP_SV
        }
        __syncthreads();
        if (t < 196) {
#pragma unroll
            for (int r = 0; r < 4; r++)
                Q[t * 4 + r] = Qpart[t * 8 + r] + Qpart[t * 8 + 4 + r];
        }
        __syncthreads();
        if (t < 224) {
            int e = t / 14, c = t - (t / 14) * 14;
            int s_ = e >> 2, r = e & 3;
            float v = 0.f;
            int pb = c * 14;
#pragma unroll
            for (int p = 0; p < 14; p++) v += sP[(pb + p) * 4 + s_] * Q[(pb + p) * 4 + r];
            redA[e * 14 + c] = v;
        } else if (t >= 256 && t < 312) {
            int e = t - 256; int j = e >> 2, r = e & 3;
            float v = 0.f;
#pragma unroll
            for (int k = 0; k < 14; k++) v += sC[k * 4 + r] * Q[(j * 14 + k) * 4 + r];
            sM[e] = v;
        }
        __syncthreads();
        if (t < 32) {
            if (t < 16) {
                float v = 0.f;
#pragma unroll
                for (int c = 0; c < 14; c++) v += redA[t * 14 + c];
                sAtA[t] = v;
            }
            __syncwarp();
            if (t < 16) inv4_warp16(sAtA, sCtC, sGi, t);
        }
        __syncthreads();
        if (t < 56) {
            int j = t >> 2, r = t & 3;
            sB[t] = sM[j * 4 + 0] * sGi[0 * 4 + r] + sM[j * 4 + 1] * sGi[1 * 4 + r] +
                    sM[j * 4 + 2] * sGi[2 * 4 + r] + sM[j * 4 + 3] * sGi[3 * 4 + r];
        }
        __syncthreads();
        if (t < 32) {
            if (t < 16) {
                int a = t >> 2, c2 = t & 3;
                float s = 0.f;
#pragma unroll
                for (int j = 0; j < 14; j++) s += sB[j * 4 + a] * sB[j * 4 + c2];
                sBtB[t] = s;
            }
            __syncwarp();
            if (t < 16) inv4_warp16(sAtA, sBtB, sGi, t);
        } else if (t >= 64 && t < 120) {
            int e = t - 64; int k = e >> 2, r = e & 3;
            float v = 0.f;
#pragma unroll
            for (int j = 0; j < 14; j++) v += sB[j * 4 + r] * Q[(j * 14 + k) * 4 + r];
            sM[e] = v;
        }
        __syncthreads();
        if (t < 56) {
            int k = t >> 2, r = t & 3;
            sC[t] = sM[k * 4 + 0] * sGi[0 * 4 + r] + sM[k * 4 + 1] * sGi[1 * 4 + r] +
                    sM[k * 4 + 2] * sGi[2 * 4 + r] + sM[k * 4 + 3] * sGi[3 * 4 + r];
        }
        __syncthreads();
    }

    if (t < 196)
        ((float4*)(g_P + (size_t)b * 784))[t] = *(const float4*)(sP + t * 4);
}

// =====================================================================
// K3: A = T0@Pt (smem-staged x), rank_fc, SE gate, APPLY. (round-13 exact)
// =====================================================================
#define A_TC   0
#define A_PT   12800
#define A_Y2   13584
#define A_RED  14096
#define A_Z    14608
#define A_W1   14640
#define A_W2   14656
#define A_G    14660
#define A_FLOATS 15172        // 60688 B

__global__ void __launch_bounds__(512, 2)
k3_gate_apply(const float* __restrict__ x, const float* __restrict__ w1,
              const float* __restrict__ w2, const float* __restrict__ fw1,
              const float* __restrict__ fw2, float* __restrict__ out)
{
    const int b = blockIdx.x;
    const int t = threadIdx.x;
    const int wid = t >> 5, lane = t & 31;
    const float* xs = x + (size_t)b * 100352;

    float4* Tc4 = (float4*)(sm + A_TC);
    float* Pt = sm + A_PT;
    float* sy2 = sm + A_Y2;
    float* red = sm + A_RED;
    float* sz = sm + A_Z;
    float* sw1 = sm + A_W1;
    float* sw2 = sm + A_W2;
    float* sg = sm + A_G;

    if (t < 196) {
        float4 p = ((const float4*)(g_P + (size_t)b * 784))[t];
        Pt[t] = p.x; Pt[196 + t] = p.y; Pt[392 + t] = p.z; Pt[588 + t] = p.w;
    } else if (t >= 448 && t < 464) sw1[t - 448] = w1[t - 448];
    else if (t >= 464 && t < 468) sw2[t - 464] = w2[t - 464];

    const int cl = t >> 3;
    const int s = t & 7;
    __syncthreads();

    for (int ch = 0; ch < 8; ch++) {
        for (int v = t; v < 3200; v += 512) {
            int i = v / 50, c4 = v - 50 * (v / 50);
            if (c4 < 49)
                Tc4[i * 50 + c4] = *(const float4*)(xs + ch * 12544 + i * 196 + c4 * 4);
        }
        __syncthreads();
        float a0 = 0, a1 = 0, a2 = 0, a3 = 0;
        if (s < 7) {
            const float* row = sm + A_TC + cl * 200;
#pragma unroll
            for (int j = 0; j < 7; j++) {
                int q = s * 28 + j * 4;
                float4 xv = *(const float4*)(row + q);
                float4 p0 = *(const float4*)(Pt + q);
                float4 p1 = *(const float4*)(Pt + 196 + q);
                float4 p2 = *(const float4*)(Pt + 392 + q);
                float4 p3 = *(const float4*)(Pt + 588 + q);
                a0 += xv.x * p0.x + xv.y * p0.y + xv.z * p0.z + xv.w * p0.w;
                a1 += xv.x * p1.x + xv.y * p1.y + xv.z * p1.z + xv.w * p1.w;
                a2 += xv.x * p2.x + xv.y * p2.y + xv.z * p2.z + xv.w * p2.w;
                a3 += xv.x * p3.x + xv.y * p3.y + xv.z * p3.z + xv.w * p3.w;
            }
        }
#pragma unroll
        for (int m = 4; m; m >>= 1) {
            a0 += __shfl_xor_sync(0xffffffffu, a0, m);
            a1 += __shfl_xor_sync(0xffffffffu, a1, m);
            a2 += __shfl_xor_sync(0xffffffffu, a2, m);
            a3 += __shfl_xor_sync(0xffffffffu, a3, m);
        }
        if (s == 0) {
            float y2 = 0.f;
#pragma unroll
            for (int s_ = 0; s_ < 4; s_++) {
                float u = a0 * sw1[s_ * 4 + 0] + a1 * sw1[s_ * 4 + 1] +
                          a2 * sw1[s_ * 4 + 2] + a3 * sw1[s_ * 4 + 3];
                u = fmaxf(u, 0.f);
                y2 += u * sw2[s_];
            }
            sy2[ch * 64 + cl] = y2;
        }
        __syncthreads();
    }
    {
        int m = t >> 4, c = t & 15;
        const float* fr = fw1 + m * 512 + c * 32;
        const float* yy = sy2 + c * 32;
        float v = 0.f;
#pragma unroll
        for (int i2 = 0; i2 < 32; i2++) v += fr[i2] * yy[i2];
        red[m * 16 + c] = v;
    }
    __syncthreads();
    if (t < 32) {
        float v = 0.f;
#pragma unroll
        for (int c = 0; c < 16; c++) v += red[t * 16 + c];
        sz[t] = fmaxf(v, 0.f);
    }
    __syncthreads();
    {
        const float* fr = fw2 + t * 32;
        float v = 0.f;
#pragma unroll
        for (int m = 0; m < 32; m++) v += fr[m] * sz[m];
        sg[t] = 1.f / (1.f + expf(-v));
    }
    __syncthreads();
    {
        const float4* xin4 = (const float4*)xs;
        float4* out4 = (float4*)(out + (size_t)b * 100352);
        for (int c = wid; c < 512; c += 16) {
            float g = sg[c];
            const float4* xr = xin4 + c * 49;
            float4* orow = out4 + c * 49;
            float4 xv = xr[lane];
            if (lane < 17) {
                float4 xv2 = xr[lane + 32];
                orow[lane + 32] = make_float4(xv2.x * g, xv2.y * g, xv2.z * g, xv2.w * g);
            }
            orow[lane] = make_float4(xv.x * g, xv.y * g, xv.z * g, xv.w * g);
        }
    }
}

extern "C" void kernel_launch(void* const* d_in, const int* in_sizes, int n_in,
                              void* d_out, int out_size) {
    const float* x   = (const float*)d_in[0];
    // d_in[1] = A0: unused (A is overwritten before first use in the reference)
    const float* B0  = (const float*)d_in[2];
    const float* C0  = (const float*)d_in[3];
    const float* w1  = (const float*)d_in[4];
    const float* w2  = (const float*)d_in[5];
    const float* fw1 = (const float*)d_in[6];
    const float* fw2 = (const float*)d_in[7];
    float* out = (float*)d_out;

    int b = in_sizes[0] / 100352;                        // 256
    size_t sm1 = (size_t)K1_FLOATS * sizeof(float);      // 72480
    size_t sm2 = (size_t)K2_FLOATS * sizeof(float);      // 108448
    size_t sm3 = (size_t)A_FLOATS * sizeof(float);       // 60688
    static int configured = 0;
    if (!configured) {
        cudaFuncSetAttribute(k1_gram,       cudaFuncAttributeMaxDynamicSharedMemorySize, (int)sm1);
        cudaFuncSetAttribute(k2_als,        cudaFuncAttributeMaxDynamicSharedMemorySize, (int)sm2);
        cudaFuncSetAttribute(k3_gate_apply, cudaFuncAttributeMaxDynamicSharedMemorySize, (int)sm3);
        configured = 1;
    }
    k1_gram<<<2 * b, 512, sm1>>>(x);
    k2_als<<<b, 512, sm2>>>(B0, C0);
    k3_gate_apply<<<b, 512, sm3>>>(x, w1, w2, fw1, fw2, out);
}

// round 16
// speedup vs baseline: 1.0522x; 1.0230x over previous
#include <cuda_runtime.h>
#include <cuda_bf16.h>
#include <cstdint>
#include <math.h>

#define EPSR 1e-6f
#define NSAMP 256

// ---------------- global scratch (static; no allocation) ----------
// S in float4-panel layout: panel g (g<49) holds cols 4g..4g+3 for all 196 rows:
//   addr(p, 4g+j) = g*784 + p*4 + j   (lane-consecutive p -> coalesced f4 reads)
__device__ float g_Sc[NSAMP * 49 * 784];     // 38416 f/sample (L2-resident)
__device__ float g_P[NSAMP * 196 * 4];       // final projection (A = T0 @ P)

__device__ __forceinline__ uint32_t smem_u32(const void* p) {
    uint32_t a;
    asm("{ .reg .u64 t; cvta.to.shared.u64 t, %1; cvt.u32.u64 %0, t; }" : "=r"(a) : "l"(p));
    return a;
}

// Warp-parallel 4x4 SPD inverse via adjugate (lanes 0..15)
__device__ __forceinline__ void inv4_warp16(const float* __restrict__ ga,
                                            const float* __restrict__ gb,
                                            float* __restrict__ gi, int t)
{
    float G[16];
#pragma unroll
    for (int e = 0; e < 16; e++)
        G[e] = ga[e] * gb[e] + ((e % 5 == 0) ? EPSR : 0.f);
    int i = t >> 2, j = t & 3;
    int r0 = (i == 0) ? 1 : 0, r1 = (i < 2) ? 2 : 1, r2 = (i < 3) ? 3 : 2;
    int c0 = (j == 0) ? 1 : 0, c1 = (j < 2) ? 2 : 1, c2 = (j < 3) ? 3 : 2;
    float a = G[r0 * 4 + c0], bb = G[r0 * 4 + c1], c = G[r0 * 4 + c2];
    float d = G[r1 * 4 + c0], e  = G[r1 * 4 + c1], f = G[r1 * 4 + c2];
    float g = G[r2 * 4 + c0], h  = G[r2 * 4 + c1], i2 = G[r2 * 4 + c2];
    float det3 = a * (e * i2 - f * h) - bb * (d * i2 - f * g) + c * (d * h - e * g);
    float cof = ((i + j) & 1) ? -det3 : det3;
    const unsigned m16 = 0x0000ffffu;
    float c0v = __shfl_sync(m16, cof, 0);
    float c1v = __shfl_sync(m16, cof, 1);
    float c2v = __shfl_sync(m16, cof, 2);
    float c3v = __shfl_sync(m16, cof, 3);
    float det = G[0] * c0v + G[1] * c1v + G[2] * c2v + G[3] * c3v;
    float cji = __shfl_sync(m16, cof, j * 4 + i);
    gi[t] = cji / det;
}

#define MMA_BF16(D, A, B)                                                         \
    asm volatile("mma.sync.aligned.m16n8k16.row.col.f32.bf16.bf16.f32 "           \
        "{%0,%1,%2,%3}, {%4,%5,%6,%7}, {%8,%9}, {%0,%1,%2,%3};"                   \
        : "+f"((D)[0]), "+f"((D)[1]), "+f"((D)[2]), "+f"((D)[3])                  \
        : "r"((A)[0]), "r"((A)[1]), "r"((A)[2]), "r"((A)[3]),                     \
          "r"((B)[0]), "r"((B)[1]))

#define LDM_X4(R, ADDR)                                                           \
    asm volatile("ldmatrix.sync.aligned.m8n8.x4.shared.b16 {%0,%1,%2,%3}, [%4];"  \
        : "=r"((R)[0]), "=r"((R)[1]), "=r"((R)[2]), "=r"((R)[3]) : "r"(ADDR))

#define LDM_X2(R, ADDR)                                                           \
    asm volatile("ldmatrix.sync.aligned.m8n8.x2.shared.b16 {%0,%1}, [%2];"        \
        : "=r"((R)[0]), "=r"((R)[1]) : "r"(ADDR))

// =====================================================================
// K1: S = T0^T T0 via mma.sync (bf16 two-term split).
// Grid 2*NSAMP: CTA (b, half) computes n-tiles [0,13) or [13,25).
// Staging remapped lane-fast-channel -> conflict-free STS.
// =====================================================================
#define K1_STG  0
#define K1_AHI  6472
#define K1_ALO  12296
#define K1_FLOATS 18120       // 72480 B

extern __shared__ float sm[];

template<int NI0, int NT>
__device__ __forceinline__ void gram_pass(const float* __restrict__ xs,
                                          float* __restrict__ gS,
                                          int t, int wid, int lane,
                                          uint32_t ahi_u32, uint32_t alo_u32)
{
    float acc[NT][4];
#pragma unroll
    for (int i = 0; i < NT; i++) {
        acc[i][0] = 0.f; acc[i][1] = 0.f; acc[i][2] = 0.f; acc[i][3] = 0.f;
    }
    float* stgT = sm + K1_STG;
    __nv_bfloat16* AH = (__nv_bfloat16*)(sm + K1_AHI);
    __nv_bfloat16* AL = (__nv_bfloat16*)(sm + K1_ALO);
    const int mi = wid;

    for (int ch = 0; ch < 16; ++ch) {
        // stage 32 channels x 196 floats TRANSPOSED: stg_T[i][c], pitch 33.
        // lane-fast channel (c = v&31) -> stride-1 STS, conflict-free.
        {
            const float4* src = (const float4*)(xs + ch * 32 * 196);
            for (int v = t; v < 1568; v += 512) {
                int c = v & 31, i4 = v >> 5;
                float4 xv = src[c * 49 + i4];
                float* d = stgT + (i4 * 4) * 33 + c;
                d[0]  = xv.x;
                d[33] = xv.y;
                d[66] = xv.z;
                d[99] = xv.w;
            }
        }
        __syncthreads();
        // convert to bf16 hi/lo: conflict-free row reads, contiguous stores
        for (int r = wid; r < 196; r += 16) {
            float v0 = stgT[r * 33 + lane];
            __nv_bfloat16 h = __float2bfloat16(v0);
            float hf = __bfloat162float(h);
            __nv_bfloat16 l = __float2bfloat16(v0 - hf);
            AH[r * 56 + lane] = h;
            AL[r * 56 + lane] = l;
        }
        __syncthreads();
        if (wid < 13) {
#pragma unroll
            for (int k16 = 0; k16 < 2; ++k16) {
                const int kof = k16 * 16;
                uint32_t aoff = (uint32_t)((mi * 16 + (lane & 15)) * 112 +
                                           (kof + ((lane >> 4) << 3)) * 2);
                uint32_t ah[4], al[4];
                LDM_X4(ah, ahi_u32 + aoff);
                LDM_X4(al, alo_u32 + aoff);
                uint32_t boff = (uint32_t)((lane & 7) * 112 + (kof + (lane & 8)) * 2);
#pragma unroll
                for (int nt = 0; nt < NT; ++nt) {
                    uint32_t bo = boff + (uint32_t)((NI0 + nt) * 8 * 112);
                    uint32_t bh[2], bl[2];
                    LDM_X2(bh, ahi_u32 + bo);
                    LDM_X2(bl, alo_u32 + bo);
                    MMA_BF16(acc[nt], ah, bh);
                    MMA_BF16(acc[nt], ah, bl);
                    MMA_BF16(acc[nt], al, bh);
                }
            }
        }
        __syncthreads();
    }
    // epilogue: registers -> g_Sc panels (float2 stores, 8B aligned)
    if (wid < 13) {
        int r0 = mi * 16 + (lane >> 2);
        int r1 = r0 + 8;
#pragma unroll
        for (int nt = 0; nt < NT; ++nt) {
            int cn = (NI0 + nt) * 8 + (lane & 3) * 2;   // even, < 200
            if (cn < 196) {
                int base = (cn >> 2) * 784 + (cn & 3);
                if (r0 < 196) *(float2*)(gS + base + r0 * 4) = make_float2(acc[nt][0], acc[nt][1]);
                if (r1 < 196) *(float2*)(gS + base + r1 * 4) = make_float2(acc[nt][2], acc[nt][3]);
            }
        }
    }
}

__global__ void __launch_bounds__(512, 2)
k1_gram(const float* __restrict__ x)
{
    const int b = blockIdx.x >> 1;
    const int half = blockIdx.x & 1;
    const int t = threadIdx.x;
    const int wid = t >> 5, lane = t & 31;
    const float* xs = x + (size_t)b * 100352;
    float* gS = g_Sc + (size_t)b * 38416;

    const uint32_t ahi_u32 = smem_u32(sm + K1_AHI);
    const uint32_t alo_u32 = smem_u32(sm + K1_ALO);

    {
        __nv_bfloat16* AH = (__nv_bfloat16*)(sm + K1_AHI);
        __nv_bfloat16* AL = (__nv_bfloat16*)(sm + K1_ALO);
        __nv_bfloat16 z = __float2bfloat16(0.f);
        if (t < 384) {
            int r = 196 + (t >> 5), c = t & 31;
            AH[r * 56 + c] = z;
            AL[r * 56 + c] = z;
        }
    }
    if (half == 0) gram_pass<0, 13>(xs, gS, t, wid, lane, ahi_u32, alo_u32);
    else           gram_pass<13, 12>(xs, gS, t, wid, lane, ahi_u32, alo_u32);
}

// =====================================================================
// K2: 20 ALS iterations; S streamed from L2 (panel layout, coalesced).
// (round-13 exact: 512 thr, 2 CTAs/SM, single wave, unroll 8)
// =====================================================================
#define K2_Q    0
#define K2_QP   784
#define K2_P    2352
#define K2_B    3136
#define K2_C    3192
#define K2_BTB  3248
#define K2_CTC  3264
#define K2_ATA  3280
#define K2_GI   3296
#define K2_M    3312
#define K2_REDA 3368
#define K2_FLOATS 3592        // 14368 B

__global__ void __launch_bounds__(512, 2)
k2_als(const float* __restrict__ B0, const float* __restrict__ C0)
{
    const int b = blockIdx.x;
    const int t = threadIdx.x;

    float* Q = sm + K2_Q;
    float* Qpart = sm + K2_QP;
    float* sP = sm + K2_P;
    float* sB = sm + K2_B;
    float* sC = sm + K2_C;
    float* sBtB = sm + K2_BTB;
    float* sCtC = sm + K2_CTC;
    float* sAtA = sm + K2_ATA;
    float* sGi = sm + K2_GI;
    float* sM = sm + K2_M;
    float* redA = sm + K2_REDA;

    const float4* Sp = (const float4*)(g_Sc + (size_t)b * 38416);  // [49][196] f4

    if (t >= 400 && t < 456) sB[t - 400] = B0[b * 56 + (t - 400)];
    else if (t >= 456 && t < 512) sC[t - 456] = C0[b * 56 + (t - 456)];
    __syncthreads();

    for (int it = 0; it < 20; it++) {
        if (t < 32) {
            int which = t >> 4, e = t & 15, a = e >> 2, c2 = e & 3;
            const float* F = which ? sC : sB;
            float s = 0.f;
#pragma unroll
            for (int j = 0; j < 14; j++) s += F[j * 4 + a] * F[j * 4 + c2];
            (which ? sCtC : sBtB)[e] = s;
            __syncwarp();
            if (t < 16) inv4_warp16(sBtB, sCtC, sGi, t);
        }
        __syncthreads();
        if (t < 196) {
            int j = t / 14, k = t - (t / 14) * 14;
            float kr0 = sB[j * 4 + 0] * sC[k * 4 + 0];
            float kr1 = sB[j * 4 + 1] * sC[k * 4 + 1];
            float kr2 = sB[j * 4 + 2] * sC[k * 4 + 2];
            float kr3 = sB[j * 4 + 3] * sC[k * 4 + 3];
#pragma unroll
            for (int r = 0; r < 4; r++)
                sP[t * 4 + r] = kr0 * sGi[0 * 4 + r] + kr1 * sGi[1 * 4 + r] +
                                kr2 * sGi[2 * 4 + r] + kr3 * sGi[3 * 4 + r];
        }
        __syncthreads();
        if (it == 19) break;                // final A needs only P

        // Q = S @ P; S streamed from L2, coalesced f4 panels, deep MLP
        if (t < 392) {
            int p = (t < 196) ? t : (t - 196);
            const float4* Pv = (const float4*)sP;
            float a0 = 0, a1 = 0, a2 = 0, a3 = 0;
            int g0 = (t < 196) ? 0 : 24;
            int g1 = (t < 196) ? 24 : 49;
#pragma unroll 8
            for (int g = g0; g < g1; ++g) {
                float4 sv = __ldg(Sp + g * 196 + p);
                float4 p0 = Pv[g * 4 + 0];
                float4 p1 = Pv[g * 4 + 1];
                float4 p2 = Pv[g * 4 + 2];
                float4 p3 = Pv[g * 4 + 3];
                a0 += sv.x * p0.x + sv.y * p1.x + sv.z * p2.x + sv.w * p3.x;
                a1 += sv.x * p0.y + sv.y * p1.y + sv.z * p2.y + sv.w * p3.y;
                a2 += sv.x * p0.z + sv.y * p1.z + sv.z * p2.z + sv.w * p3.z;
                a3 += sv.x * p0.w + sv.y * p1.w + sv.z * p2.w + sv.w * p3.w;
            }
            int h = (t < 196) ? 0 : 1;
            Qpart[p * 8 + h * 4 + 0] = a0;
            Qpart[p * 8 + h * 4 + 1] = a1;
            Qpart[p * 8 + h * 4 + 2] = a2;
            Qpart[p * 8 + h * 4 + 3] = a3;
        }
        __syncthreads();
        if (t < 196) {
#pragma unroll
            for (int r = 0; r < 4; r++)
                Q[t * 4 + r] = Qpart[t * 8 + r] + Qpart[t * 8 + 4 + r];
        }
        __syncthreads();
        if (t < 224) {
            int e = t / 14, c = t - (t / 14) * 14;
            int s_ = e >> 2, r = e & 3;
            float v = 0.f;
            int pb = c * 14;
#pragma unroll
            for (int p = 0; p < 14; p++) v += sP[(pb + p) * 4 + s_] * Q[(pb + p) * 4 + r];
            redA[e * 14 + c] = v;
        } else if (t >= 256 && t < 312) {
            int e = t - 256; int j = e >> 2, r = e & 3;
            float v = 0.f;
#pragma unroll
            for (int k = 0; k < 14; k++) v += sC[k * 4 + r] * Q[(j * 14 + k) * 4 + r];
            sM[e] = v;
        }
        __syncthreads();
        if (t < 32) {
            if (t < 16) {
                float v = 0.f;
#pragma unroll
                for (int c = 0; c < 14; c++) v += redA[t * 14 + c];
                sAtA[t] = v;
            }
            __syncwarp();
            if (t < 16) inv4_warp16(sAtA, sCtC, sGi, t);
        }
        __syncthreads();
        if (t < 56) {
            int j = t >> 2, r = t & 3;
            sB[t] = sM[j * 4 + 0] * sGi[0 * 4 + r] + sM[j * 4 + 1] * sGi[1 * 4 + r] +
                    sM[j * 4 + 2] * sGi[2 * 4 + r] + sM[j * 4 + 3] * sGi[3 * 4 + r];
        }
        __syncthreads();
        if (t < 32) {
            if (t < 16) {
                int a = t >> 2, c2 = t & 3;
                float s = 0.f;
#pragma unroll
                for (int j = 0; j < 14; j++) s += sB[j * 4 + a] * sB[j * 4 + c2];
                sBtB[t] = s;
            }
            __syncwarp();
            if (t < 16) inv4_warp16(sAtA, sBtB, sGi, t);
        } else if (t >= 64 && t < 120) {
            int e = t - 64; int k = e >> 2, r = e & 3;
            float v = 0.f;
#pragma unroll
            for (int j = 0; j < 14; j++) v += sB[j * 4 + r] * Q[(j * 14 + k) * 4 + r];
            sM[e] = v;
        }
        __syncthreads();
        if (t < 56) {
            int k = t >> 2, r = t & 3;
            sC[t] = sM[k * 4 + 0] * sGi[0 * 4 + r] + sM[k * 4 + 1] * sGi[1 * 4 + r] +
                    sM[k * 4 + 2] * sGi[2 * 4 + r] + sM[k * 4 + 3] * sGi[3 * 4 + r];
        }
        __syncthreads();
    }

    if (t < 196)
        ((float4*)(g_P + (size_t)b * 784))[t] = *(const float4*)(sP + t * 4);
}

// =====================================================================
// K3: A = T0@Pt (smem-staged x), rank_fc, SE gate, APPLY. (round-13 exact)
// =====================================================================
#define A_TC   0
#define A_PT   12800
#define A_Y2   13584
#define A_RED  14096
#define A_Z    14608
#define A_W1   14640
#define A_W2   14656
#define A_G    14660
#define A_FLOATS 15172        // 60688 B

__global__ void __launch_bounds__(512, 2)
k3_gate_apply(const float* __restrict__ x, const float* __restrict__ w1,
              const float* __restrict__ w2, const float* __restrict__ fw1,
              const float* __restrict__ fw2, float* __restrict__ out)
{
    const int b = blockIdx.x;
    const int t = threadIdx.x;
    const int wid = t >> 5, lane = t & 31;
    const float* xs = x + (size_t)b * 100352;

    float4* Tc4 = (float4*)(sm + A_TC);
    float* Pt = sm + A_PT;
    float* sy2 = sm + A_Y2;
    float* red = sm + A_RED;
    float* sz = sm + A_Z;
    float* sw1 = sm + A_W1;
    float* sw2 = sm + A_W2;
    float* sg = sm + A_G;

    if (t < 196) {
        float4 p = ((const float4*)(g_P + (size_t)b * 784))[t];
        Pt[t] = p.x; Pt[196 + t] = p.y; Pt[392 + t] = p.z; Pt[588 + t] = p.w;
    } else if (t >= 448 && t < 464) sw1[t - 448] = w1[t - 448];
    else if (t >= 464 && t < 468) sw2[t - 464] = w2[t - 464];

    const int cl = t >> 3;
    const int s = t & 7;
    __syncthreads();

    for (int ch = 0; ch < 8; ch++) {
        for (int v = t; v < 3200; v += 512) {
            int i = v / 50, c4 = v - 50 * (v / 50);
            if (c4 < 49)
                Tc4[i * 50 + c4] = *(const float4*)(xs + ch * 12544 + i * 196 + c4 * 4);
        }
        __syncthreads();
        float a0 = 0, a1 = 0, a2 = 0, a3 = 0;
        if (s < 7) {
            const float* row = sm + A_TC + cl * 200;
#pragma unroll
            for (int j = 0; j < 7; j++) {
                int q = s * 28 + j * 4;
                float4 xv = *(const float4*)(row + q);
                float4 p0 = *(const float4*)(Pt + q);
                float4 p1 = *(const float4*)(Pt + 196 + q);
                float4 p2 = *(const float4*)(Pt + 392 + q);
                float4 p3 = *(const float4*)(Pt + 588 + q);
                a0 += xv.x * p0.x + xv.y * p0.y + xv.z * p0.z + xv.w * p0.w;
                a1 += xv.x * p1.x + xv.y * p1.y + xv.z * p1.z + xv.w * p1.w;
                a2 += xv.x * p2.x + xv.y * p2.y + xv.z * p2.z + xv.w * p2.w;
                a3 += xv.x * p3.x + xv.y * p3.y + xv.z * p3.z + xv.w * p3.w;
            }
        }
#pragma unroll
        for (int m = 4; m; m >>= 1) {
            a0 += __shfl_xor_sync(0xffffffffu, a0, m);
            a1 += __shfl_xor_sync(0xffffffffu, a1, m);
            a2 += __shfl_xor_sync(0xffffffffu, a2, m);
            a3 += __shfl_xor_sync(0xffffffffu, a3, m);
        }
        if (s == 0) {
            float y2 = 0.f;
#pragma unroll
            for (int s_ = 0; s_ < 4; s_++) {
                float u = a0 * sw1[s_ * 4 + 0] + a1 * sw1[s_ * 4 + 1] +
                          a2 * sw1[s_ * 4 + 2] + a3 * sw1[s_ * 4 + 3];
                u = fmaxf(u, 0.f);
                y2 += u * sw2[s_];
            }
            sy2[ch * 64 + cl] = y2;
        }
        __syncthreads();
    }
    {
        int m = t >> 4, c = t & 15;
        const float* fr = fw1 + m * 512 + c * 32;
        const float* yy = sy2 + c * 32;
        float v = 0.f;
#pragma unroll
        for (int i2 = 0; i2 < 32; i2++) v += fr[i2] * yy[i2];
        red[m * 16 + c] = v;
    }
    __syncthreads();
    if (t < 32) {
        float v = 0.f;
#pragma unroll
        for (int c = 0; c < 16; c++) v += red[t * 16 + c];
        sz[t] = fmaxf(v, 0.f);
    }
    __syncthreads();
    {
        const float* fr = fw2 + t * 32;
        float v = 0.f;
#pragma unroll
        for (int m = 0; m < 32; m++) v += fr[m] * sz[m];
        sg[t] = 1.f / (1.f + expf(-v));
    }
    __syncthreads();
    {
        const float4* xin4 = (const float4*)xs;
        float4* out4 = (float4*)(out + (size_t)b * 100352);
        for (int c = wid; c < 512; c += 16) {
            float g = sg[c];
            const float4* xr = xin4 + c * 49;
            float4* orow = out4 + c * 49;
            float4 xv = xr[lane];
            if (lane < 17) {
                float4 xv2 = xr[lane + 32];
                orow[lane + 32] = make_float4(xv2.x * g, xv2.y * g, xv2.z * g, xv2.w * g);
            }
            orow[lane] = make_float4(xv.x * g, xv.y * g, xv.z * g, xv.w * g);
        }
    }
}

extern "C" void kernel_launch(void* const* d_in, const int* in_sizes, int n_in,
                              void* d_out, int out_size) {
    const float* x   = (const float*)d_in[0];
    // d_in[1] = A0: unused (A is overwritten before first use in the reference)
    const float* B0  = (const float*)d_in[2];
    const float* C0  = (const float*)d_in[3];
    const float* w1  = (const float*)d_in[4];
    const float* w2  = (const float*)d_in[5];
    const float* fw1 = (const float*)d_in[6];
    const float* fw2 = (const float*)d_in[7];
    float* out = (float*)d_out;

    int b = in_sizes[0] / 100352;                        // 256
    size_t sm1 = (size_t)K1_FLOATS * sizeof(float);      // 72480
    size_t sm2 = (size_t)K2_FLOATS * sizeof(float);      // 14368
    size_t sm3 = (size_t)A_FLOATS * sizeof(float);       // 60688
    static int configured = 0;
    if (!configured) {
        cudaFuncSetAttribute(k1_gram,       cudaFuncAttributeMaxDynamicSharedMemorySize, (int)sm1);
        cudaFuncSetAttribute(k2_als,        cudaFuncAttributeMaxDynamicSharedMemorySize, (int)sm2);
        cudaFuncSetAttribute(k3_gate_apply, cudaFuncAttributeMaxDynamicSharedMemorySize, (int)sm3);
        configured = 1;
    }
    k1_gram<<<2 * b, 512, sm1>>>(x);
    k2_als<<<b, 512, sm2>>>(B0, C0);
    k3_gate_apply<<<b, 512, sm3>>>(x, w1, w2, fw1, fw2, out);
}